// round 12
// baseline (speedup 1.0000x reference)
#include <cuda_runtime.h>
#include <cuda_bf16.h>
#include <math.h>
#include <cstdint>

// Problem constants
#define NN   307
#define TT   12
#define BB   128
#define DIN  2
#define DOUT 64
#define DE   10
#define NNP  320                  // padded node dim (k-dim for mma, mult of 16)

#define BND   (BB*NN*DOUT)        // 2,514,944
#define CURSZ (BB*TT*NN*DOUT)     // 30,179,328
#define BT    (BB*TT)             // 1536

// ---------------------------------------------------------------------------
// Device scratch
// ---------------------------------------------------------------------------
__device__ float g_Wg0[NN*132*128];
__device__ float g_Wu0[NN*132*64];
__device__ float g_Wg1[NN*256*128];
__device__ float g_Wu1[NN*256*64];
__device__ float g_bg0[NN*128];
__device__ float g_bu0[NN*64];
__device__ float g_bg1[NN*128];
__device__ float g_bu1[NN*64];

__device__ __nv_bfloat16 g_adjH[NNP*NNP];   // adj [n][m] bf16 hi plane, zero-padded
__device__ __nv_bfloat16 g_adjL[NNP*NNP];   // adj [n][m] bf16 lo plane

// per-layer f32 state
__device__ float g_h0  [BND];
__device__ float g_zh0 [BND];
__device__ float g_r0  [BND];
__device__ float g_Gh0 [BND];
__device__ float g_Gzh0[BND];
__device__ float g_h1  [BND];
__device__ float g_zh1 [BND];
__device__ float g_r1  [BND];
__device__ float g_Gh1 [BND];
__device__ float g_Gzh1[BND];

// pre-split bf16 hi/lo planes of propagation inputs (written by epilogues)
__device__ __nv_bfloat16 g_h0H [BND], g_h0L [BND];
__device__ __nv_bfloat16 g_zh0H[BND], g_zh0L[BND];
__device__ __nv_bfloat16 g_h1H [BND], g_h1L [BND];
__device__ __nv_bfloat16 g_zh1H[BND], g_zh1L[BND];
__device__ __nv_bfloat16 g_seqH[CURSZ], g_seqL[CURSZ];

__device__ float g_Gx2 [BT*NN*DIN];   // adj @ x (layer0, all t) [B,T,N,2]
__device__ float g_Gxall[CURSZ];      // adj @ seq0[t] for all t [B,T,N,64]
__device__ float g_seq0[CURSZ];       // layer0 output sequence [B,T,N,64]

__device__ __forceinline__ float sigm(float v) { return 1.0f / (1.0f + expf(-v)); }

// packed fp32x2 helpers (GEMMs)
__device__ __forceinline__ unsigned long long pk2(float x, float y) {
    unsigned long long r;
    asm("mov.b64 %0, {%1, %2};" : "=l"(r) : "f"(x), "f"(y));
    return r;
}
__device__ __forceinline__ unsigned long long ffma2(unsigned long long a,
                                                    unsigned long long b,
                                                    unsigned long long c) {
    unsigned long long d;
    asm("fma.rn.f32x2 %0, %1, %2, %3;" : "=l"(d) : "l"(a), "l"(b), "l"(c));
    return d;
}
__device__ __forceinline__ void unpk2(unsigned long long v, float& lo, float& hi) {
    asm("mov.b64 {%0, %1}, %2;" : "=f"(lo), "=f"(hi) : "l"(v));
}

// bf16 mma.sync m16n8k16
__device__ __forceinline__ void mma_bf16(float* c, const uint32_t* a,
                                         uint32_t b0, uint32_t b1) {
    asm volatile(
        "mma.sync.aligned.m16n8k16.row.col.f32.bf16.bf16.f32 "
        "{%0,%1,%2,%3}, {%4,%5,%6,%7}, {%8,%9}, {%0,%1,%2,%3};"
        : "+f"(c[0]), "+f"(c[1]), "+f"(c[2]), "+f"(c[3])
        : "r"(a[0]), "r"(a[1]), "r"(a[2]), "r"(a[3]), "r"(b0), "r"(b1));
}

// split 4 f32 into hi/lo bf16 quads packed as u64 (hi plane, lo plane)
__device__ __forceinline__ void split4(float4 v, unsigned long long& hp,
                                       unsigned long long& lp) {
    __nv_bfloat16 h0 = __float2bfloat16(v.x);
    __nv_bfloat16 h1 = __float2bfloat16(v.y);
    __nv_bfloat16 h2 = __float2bfloat16(v.z);
    __nv_bfloat16 h3 = __float2bfloat16(v.w);
    __nv_bfloat16 l0 = __float2bfloat16(v.x - __bfloat162float(h0));
    __nv_bfloat16 l1 = __float2bfloat16(v.y - __bfloat162float(h1));
    __nv_bfloat16 l2 = __float2bfloat16(v.z - __bfloat162float(h2));
    __nv_bfloat16 l3 = __float2bfloat16(v.w - __bfloat162float(h3));
    uint16_t a0 = *(uint16_t*)&h0, a1 = *(uint16_t*)&h1;
    uint16_t a2 = *(uint16_t*)&h2, a3 = *(uint16_t*)&h3;
    uint16_t b0 = *(uint16_t*)&l0, b1 = *(uint16_t*)&l1;
    uint16_t b2 = *(uint16_t*)&l2, b3 = *(uint16_t*)&l3;
    hp = (unsigned long long)a0 | ((unsigned long long)a1 << 16)
       | ((unsigned long long)a2 << 32) | ((unsigned long long)a3 << 48);
    lp = (unsigned long long)b0 | ((unsigned long long)b1 << 16)
       | ((unsigned long long)b2 << 32) | ((unsigned long long)b3 << 48);
}

// ---------------------------------------------------------------------------
// prep kernels
// ---------------------------------------------------------------------------
#define S_WG0 (132*128)
#define S_WU0 (132*64)
#define S_WG1 (256*128)
#define S_WU1 (256*64)
#define C0 ((long)NN*S_WG0)
#define C1 (C0 + (long)NN*S_WU0)
#define C2 (C1 + (long)NN*S_WG1)
#define C3 (C2 + (long)NN*S_WU1)
#define C4 (C3 + (long)NN*128)
#define C5 (C4 + (long)NN*64)
#define C6 (C5 + (long)NN*128)
#define C7 (C6 + (long)NN*64)

__global__ void prep_all(const float* __restrict__ E,
                         const float* __restrict__ wg0, const float* __restrict__ wu0,
                         const float* __restrict__ wg1, const float* __restrict__ wu1,
                         const float* __restrict__ bg0, const float* __restrict__ bu0,
                         const float* __restrict__ bg1, const float* __restrict__ bu1) {
    long idx = (long)blockIdx.x * blockDim.x + threadIdx.x;
    if (idx >= C7) return;
    const float* pool; float* out; long loc; int S;
    if      (idx < C0) { pool = wg0; out = g_Wg0; loc = idx;      S = S_WG0; }
    else if (idx < C1) { pool = wu0; out = g_Wu0; loc = idx - C0; S = S_WU0; }
    else if (idx < C2) { pool = wg1; out = g_Wg1; loc = idx - C1; S = S_WG1; }
    else if (idx < C3) { pool = wu1; out = g_Wu1; loc = idx - C2; S = S_WU1; }
    else if (idx < C4) { pool = bg0; out = g_bg0; loc = idx - C3; S = 128;   }
    else if (idx < C5) { pool = bu0; out = g_bu0; loc = idx - C4; S = 64;    }
    else if (idx < C6) { pool = bg1; out = g_bg1; loc = idx - C5; S = 128;   }
    else               { pool = bu1; out = g_bu1; loc = idx - C6; S = 64;    }
    int n = (int)(loc / S);
    long j = loc - (long)n * S;
    float acc = 0.0f;
#pragma unroll
    for (int d = 0; d < DE; d++)
        acc += E[n*DE + d] * pool[(long)d*S + j];
    out[loc] = acc;
}

// adj -> bf16 hi/lo planes, [n][m] layout, zero-padded to 320x320
__global__ void prep_adjB(const float* __restrict__ adj) {
    int i = blockIdx.x * blockDim.x + threadIdx.x;
    if (i >= NNP*NNP) return;
    int n = i / NNP, m = i - n*NNP;
    float v = (n < NN && m < NN) ? adj[(long)n*NN + m] : 0.0f;
    __nv_bfloat16 h = __float2bfloat16(v);
    __nv_bfloat16 l = __float2bfloat16(v - __bfloat162float(h));
    g_adjH[i] = h;
    g_adjL[i] = l;
}

__global__ void init_h(const float* __restrict__ init, int l) {
    int i = blockIdx.x * blockDim.x + threadIdx.x;
    if (i < BND) {
        float v = init[(long)l*BND + i];
        __nv_bfloat16 h = __float2bfloat16(v);
        __nv_bfloat16 lo = __float2bfloat16(v - __bfloat162float(h));
        if (l == 0) { g_h0[i] = v; g_h0H[i] = h; g_h0L[i] = lo; }
        else        { g_h1[i] = v; g_h1H[i] = h; g_h1L[i] = lo; }
    }
}

// ---------------------------------------------------------------------------
// adj @ x for all timesteps (layer0, 2 channels): one launch, f32 (tiny)
// ---------------------------------------------------------------------------
__global__ void __launch_bounds__(256) graph_x2_all(const float* __restrict__ adj,
                                                    const float* __restrict__ x) {
    int n0  = blockIdx.x * 64;
    int bt0 = blockIdx.y * 64;
    int tid = threadIdx.x;
    int tx  = tid & 15;
    int ty  = tid >> 4;

    __shared__ float adjs[32][65];
    __shared__ float xs[64][65];

    float acc[4][4][2] = {};

    for (int m0 = 0; m0 < NN; m0 += 32) {
#pragma unroll
        for (int j = 0; j < 8; j++) {
            int lin = tid + j*256;
            int nl = lin >> 5, ml = lin & 31;
            int n = n0 + nl, m = m0 + ml;
            adjs[ml][nl] = (n < NN && m < NN) ? adj[(long)n*NN + m] : 0.0f;
        }
#pragma unroll
        for (int j = 0; j < 16; j++) {
            int lin = tid + j*256;
            int mc = lin & 63;
            int bt = lin >> 6;
            int m = m0 + (mc >> 1);
            xs[mc][bt] = (m < NN) ? x[((long)(bt0 + bt)*NN + m)*2 + (mc & 1)] : 0.0f;
        }
        __syncthreads();
#pragma unroll
        for (int ml = 0; ml < 32; ml++) {
            float a0 = adjs[ml][ty*4+0];
            float a1 = adjs[ml][ty*4+1];
            float a2 = adjs[ml][ty*4+2];
            float a3 = adjs[ml][ty*4+3];
#pragma unroll
            for (int jj = 0; jj < 4; jj++) {
                float x0 = xs[ml*2+0][tx*4+jj];
                float x1 = xs[ml*2+1][tx*4+jj];
                acc[0][jj][0] += a0*x0; acc[0][jj][1] += a0*x1;
                acc[1][jj][0] += a1*x0; acc[1][jj][1] += a1*x1;
                acc[2][jj][0] += a2*x0; acc[2][jj][1] += a2*x1;
                acc[3][jj][0] += a3*x0; acc[3][jj][1] += a3*x1;
            }
        }
        __syncthreads();
    }
#pragma unroll
    for (int i = 0; i < 4; i++) {
        int n = n0 + ty*4 + i;
        if (n >= NN) continue;
#pragma unroll
        for (int jj = 0; jj < 4; jj++) {
            int bt = bt0 + tx*4 + jj;
            *(float2*)&g_Gx2[((long)bt*NN + n)*2] =
                make_float2(acc[i][jj][0], acc[i][jj][1]);
        }
    }
}

// ---------------------------------------------------------------------------
// Graph propagation via bf16 split mma. B operand read from PRE-SPLIT planes
// (no runtime cvt). Per block: 64n x 64c x 1b; 8 warps as 4(m16) x 2(n32).
// grid (5, 128).  srcsel: 0=h0, 1=zh0, 2=seq0[t], 3=h1, 4=zh1
// dstsel: 0=Gh0, 1=Gzh0, 2=Gxall[t], 3=Gh1, 4=Gzh1
// ---------------------------------------------------------------------------
__global__ void __launch_bounds__(256) graph64_mma(int srcsel, int t, int dstsel) {
    const __nv_bfloat16 *srcH, *srcL;
    long sstride = (long)NN*DOUT;
    switch (srcsel) {
        case 0:  srcH = g_h0H;  srcL = g_h0L;  break;
        case 1:  srcH = g_zh0H; srcL = g_zh0L; break;
        case 2:  srcH = g_seqH + (long)t*NN*DOUT;
                 srcL = g_seqL + (long)t*NN*DOUT;
                 sstride = (long)TT*NN*DOUT; break;
        case 3:  srcH = g_h1H;  srcL = g_h1L;  break;
        default: srcH = g_zh1H; srcL = g_zh1L; break;
    }
    float* dst; long dstride = (long)NN*DOUT;
    switch (dstsel) {
        case 0:  dst = g_Gh0;  break;
        case 1:  dst = g_Gzh0; break;
        case 2:  dst = g_Gxall + (long)t*NN*DOUT; dstride = (long)TT*NN*DOUT; break;
        case 3:  dst = g_Gh1;  break;
        default: dst = g_Gzh1; break;
    }

    int n0  = blockIdx.x * 64;
    int b   = blockIdx.y;
    int tid = threadIdx.x;
    int lane = tid & 31;
    int wid  = tid >> 5;
    int wm = wid & 3;            // m16 tile: rows n0 + wm*16
    int wn = wid >> 2;           // n32 tile: cols wn*32

    __shared__ __nv_bfloat16 Ah[64][20], Al[64][20];   // A: [n][m16]
    __shared__ __nv_bfloat16 Bh[64][20], Bl[64][20];   // B: [c][m16]

    float acc[4][4];
#pragma unroll
    for (int i = 0; i < 4; i++)
#pragma unroll
        for (int j = 0; j < 4; j++) acc[i][j] = 0.0f;

    const __nv_bfloat16* sbH = srcH + (long)b * sstride;
    const __nv_bfloat16* sbL = srcL + (long)b * sstride;
    int bc = tid & 63;           // B fill: channel
    int bm = (tid >> 6) * 4;     // B fill: first of 4 k rows

    for (int m0 = 0; m0 < NNP; m0 += 16) {
        // A fill: u32 = 2 bf16 per plane
#pragma unroll
        for (int j = 0; j < 2; j++) {
            int lin = tid + j*256;
            int nl = lin >> 3, kp = lin & 7;
            long src_off = (long)(n0 + nl)*NNP + m0 + kp*2;
            *(uint32_t*)&Ah[nl][kp*2] = *(const uint32_t*)&g_adjH[src_off];
            *(uint32_t*)&Al[nl][kp*2] = *(const uint32_t*)&g_adjL[src_off];
        }
        // B fill: plane copies (no cvt)
#pragma unroll
        for (int i = 0; i < 4; i++) {
            int ml = bm + i;
            int m  = m0 + ml;
            uint16_t hv = 0, lv = 0;
            if (m < NN) {
                long o = (long)m*DOUT + bc;
                hv = *(const uint16_t*)&sbH[o];
                lv = *(const uint16_t*)&sbL[o];
            }
            *(uint16_t*)&Bh[bc][ml] = hv;
            *(uint16_t*)&Bl[bc][ml] = lv;
        }
        __syncthreads();

        uint32_t a_h[4], a_l[4];
#pragma unroll
        for (int j = 0; j < 4; j++) {
            int row = wm*16 + (lane >> 2) + (j & 1)*8;
            int kp  = (lane & 3)*2 + (j & 2)*4;
            a_h[j] = *(const uint32_t*)&Ah[row][kp];
            a_l[j] = *(const uint32_t*)&Al[row][kp];
        }
#pragma unroll
        for (int tn = 0; tn < 4; tn++) {
            int cc  = wn*32 + tn*8 + (lane >> 2);
            int k0p = (lane & 3)*2;
            uint32_t b_h0 = *(const uint32_t*)&Bh[cc][k0p];
            uint32_t b_h1 = *(const uint32_t*)&Bh[cc][k0p + 8];
            uint32_t b_l0 = *(const uint32_t*)&Bl[cc][k0p];
            uint32_t b_l1 = *(const uint32_t*)&Bl[cc][k0p + 8];
            mma_bf16(acc[tn], a_h, b_h0, b_h1);
            mma_bf16(acc[tn], a_h, b_l0, b_l1);
            mma_bf16(acc[tn], a_l, b_h0, b_h1);
        }
        __syncthreads();
    }

    long db = (long)b * dstride;
#pragma unroll
    for (int tn = 0; tn < 4; tn++) {
        int n = n0 + wm*16 + (lane >> 2);
        int c = wn*32 + tn*8 + (lane & 3)*2;
        if (n < NN)
            *(float2*)&dst[db + (long)n*DOUT + c] =
                make_float2(acc[tn][0], acc[tn][1]);
        if (n + 8 < NN)
            *(float2*)&dst[db + (long)(n + 8)*DOUT + c] =
                make_float2(acc[tn][2], acc[tn][3]);
    }
}

// ---------------------------------------------------------------------------
// A-row gather: A[b, kk] = [ x(CIN) | h_or_zh(64) | Gx(CIN) | Gh_or_Gzh(64) ]
// ---------------------------------------------------------------------------
template<int CIN, int MODE>
__device__ __forceinline__ float gatherA(const float* __restrict__ xext,
                                         int b, int n, int t, int kk) {
    long hoff = ((long)b*NN + n)*64;
    if (CIN == 2) {
        if (kk >= 132) return 0.0f;
        long xoff = ((long)b*TT + t)*NN*2 + (long)n*2;
        if (kk < 2)   return xext[xoff + kk];
        if (kk < 66)  return (MODE ? g_zh0 : g_h0)[hoff + (kk - 2)];
        if (kk < 68)  return g_Gx2[xoff + (kk - 66)];
        return (MODE ? g_Gzh0 : g_Gh0)[hoff + (kk - 68)];
    } else {
        long xoff = ((long)b*TT + t)*NN*64 + (long)n*64;
        if (kk < 64)  return g_seq0[xoff + kk];
        if (kk < 128) return (MODE ? g_zh1 : g_h1)[hoff + (kk - 64)];
        if (kk < 192) return g_Gxall[xoff + (kk - 128)];
        return (MODE ? g_Gzh1 : g_Gh1)[hoff + (kk - 192)];
    }
}

// ---------------------------------------------------------------------------
// Gate GEMM, oh-merged: tile 64b x 128o, 256 threads, 8b x 4o per thread.
// z half writes zh f32 + bf16 hi/lo planes. grid (NN, 2 bhalf).
// ---------------------------------------------------------------------------
template<int CIN>
__global__ void __launch_bounds__(256, 4) gate_k(const float* __restrict__ xext, int t) {
    constexpr int KD  = 2*CIN + 2*DOUT;
    constexpr int NKT = (KD + 31) / 32;
    const float* W    = (CIN == 2) ? g_Wg0 : g_Wg1;
    const float* bias = (CIN == 2) ? g_bg0 : g_bg1;
    const float* hbuf = (CIN == 2) ? g_h0  : g_h1;
    float* zhbuf      = (CIN == 2) ? g_zh0 : g_zh1;
    float* rbuf       = (CIN == 2) ? g_r0  : g_r1;
    __nv_bfloat16* zhH = (CIN == 2) ? g_zh0H : g_zh1H;
    __nv_bfloat16* zhL = (CIN == 2) ? g_zh0L : g_zh1L;

    int n  = blockIdx.x;
    int bh = blockIdx.y;
    int tid = threadIdx.x;
    int tx = tid & 31;          // o group (4 cols, 32 groups = 128 o)
    int ty = tid >> 5;          // b group (8 rows)

    __shared__ float As[32][68];    // [kk][b]
    __shared__ float Ws[32][132];   // [kk][o]

    unsigned long long acc2[8][2];
#pragma unroll
    for (int i = 0; i < 8; i++) { acc2[i][0] = 0ull; acc2[i][1] = 0ull; }

    for (int kt = 0; kt < NKT; kt++) {
        int k0 = kt * 32;
#pragma unroll
        for (int j = 0; j < 8; j++) {
            int lin = tid + j*256;
            int kl = lin & 31;
            int b  = lin >> 5;
            As[kl][b] = gatherA<CIN,0>(xext, bh*64 + b, n, t, k0 + kl);
        }
#pragma unroll
        for (int j = 0; j < 4; j++) {
            int lin = tid + j*256;
            int c4  = lin & 31;
            int row = lin >> 5;
            int kk = k0 + row;
            float4 v = make_float4(0.f, 0.f, 0.f, 0.f);
            if (kk < KD)
                v = *(const float4*)&W[((long)n*KD + kk)*128 + c4*4];
            *(float4*)&Ws[row][c4*4] = v;
        }
        __syncthreads();
#pragma unroll
        for (int k = 0; k < 32; k++) {
            float4 aLo = *(const float4*)&As[k][ty*8];
            float4 aHi = *(const float4*)&As[k][ty*8 + 4];
            ulonglong2 w2 = *(const ulonglong2*)&Ws[k][tx*4];
            float av[8] = {aLo.x, aLo.y, aLo.z, aLo.w,
                           aHi.x, aHi.y, aHi.z, aHi.w};
#pragma unroll
            for (int i = 0; i < 8; i++) {
                unsigned long long ad = pk2(av[i], av[i]);
                acc2[i][0] = ffma2(ad, w2.x, acc2[i][0]);
                acc2[i][1] = ffma2(ad, w2.y, acc2[i][1]);
            }
        }
        __syncthreads();
    }

    int o0 = tx*4;
    float4 bv = *(const float4*)&bias[n*128 + o0];
    bool isZ = (o0 < 64);
    int oc = isZ ? o0 : (o0 - 64);
#pragma unroll
    for (int i = 0; i < 8; i++) {
        int b = bh*64 + ty*8 + i;
        long hb = ((long)b*NN + n)*64 + oc;
        float v0, v1, v2, v3;
        unpk2(acc2[i][0], v0, v1);
        unpk2(acc2[i][1], v2, v3);
        v0 = sigm(v0 + bv.x); v1 = sigm(v1 + bv.y);
        v2 = sigm(v2 + bv.z); v3 = sigm(v3 + bv.w);
        if (isZ) {
            float4 hv = *(const float4*)&hbuf[hb];
            float4 o = make_float4(v0*hv.x, v1*hv.y, v2*hv.z, v3*hv.w);
            *(float4*)&zhbuf[hb] = o;
            unsigned long long hp, lp;
            split4(o, hp, lp);
            *(unsigned long long*)&zhH[hb] = hp;
            *(unsigned long long*)&zhL[hb] = lp;
        } else {
            *(float4*)&rbuf[hb] = make_float4(v0, v1, v2, v3);
        }
    }
}

// ---------------------------------------------------------------------------
// Candidate GEMM (NO=64) + GRU update; writes h f32 + bf16 planes
// (+ seq0 f32 and planes for layer0). tile 64b x 64o, grid (NN, 2).
// ---------------------------------------------------------------------------
template<int CIN>
__global__ void __launch_bounds__(128, 8) cand_k(const float* __restrict__ xext, int t,
                                                 float* __restrict__ curOut,
                                                 float* __restrict__ lastOut) {
    constexpr int KD  = 2*CIN + 2*DOUT;
    constexpr int NKT = (KD + 31) / 32;
    const float* W    = (CIN == 2) ? g_Wu0 : g_Wu1;
    const float* bias = (CIN == 2) ? g_bu0 : g_bu1;
    float* hbuf       = (CIN == 2) ? g_h0  : g_h1;
    const float* rbuf = (CIN == 2) ? g_r0  : g_r1;
    __nv_bfloat16* hH = (CIN == 2) ? g_h0H : g_h1H;
    __nv_bfloat16* hL = (CIN == 2) ? g_h0L : g_h1L;

    int n  = blockIdx.x;
    int bh = blockIdx.y;
    int tid = threadIdx.x;
    int tx = tid & 15;
    int ty = tid >> 4;

    __shared__ float As[32][68];
    __shared__ float Ws[32][68];

    unsigned long long acc2[8][2];
#pragma unroll
    for (int i = 0; i < 8; i++) { acc2[i][0] = 0ull; acc2[i][1] = 0ull; }

    for (int kt = 0; kt < NKT; kt++) {
        int k0 = kt * 32;
#pragma unroll
        for (int j = 0; j < 16; j++) {
            int lin = tid + j*128;
            int kl = lin & 31;
            int b  = lin >> 5;
            As[kl][b] = gatherA<CIN,1>(xext, bh*64 + b, n, t, k0 + kl);
        }
#pragma unroll
        for (int j = 0; j < 4; j++) {
            int lin = tid + j*128;
            int c4  = lin & 15;
            int row = lin >> 4;
            int kk = k0 + row;
            float4 v = make_float4(0.f, 0.f, 0.f, 0.f);
            if (kk < KD)
                v = *(const float4*)&W[((long)n*KD + kk)*64 + c4*4];
            *(float4*)&Ws[row][c4*4] = v;
        }
        __syncthreads();
#pragma unroll
        for (int k = 0; k < 32; k++) {
            float4 aLo = *(const float4*)&As[k][ty*8];
            float4 aHi = *(const float4*)&As[k][ty*8 + 4];
            ulonglong2 w2 = *(const ulonglong2*)&Ws[k][tx*4];
            float av[8] = {aLo.x, aLo.y, aLo.z, aLo.w,
                           aHi.x, aHi.y, aHi.z, aHi.w};
#pragma unroll
            for (int i = 0; i < 8; i++) {
                unsigned long long ad = pk2(av[i], av[i]);
                acc2[i][0] = ffma2(ad, w2.x, acc2[i][0]);
                acc2[i][1] = ffma2(ad, w2.y, acc2[i][1]);
            }
        }
        __syncthreads();
    }

    float4 bv = *(const float4*)&bias[n*64 + tx*4];
#pragma unroll
    for (int i = 0; i < 8; i++) {
        int b = bh*64 + ty*8 + i;
        long hb = ((long)b*NN + n)*64 + tx*4;
        float c0, c1, c2, c3;
        unpk2(acc2[i][0], c0, c1);
        unpk2(acc2[i][1], c2, c3);
        c0 = tanhf(c0 + bv.x); c1 = tanhf(c1 + bv.y);
        c2 = tanhf(c2 + bv.z); c3 = tanhf(c3 + bv.w);
        float4 rv = *(const float4*)&rbuf[hb];
        float4 hv = *(const float4*)&hbuf[hb];
        float4 o;
        o.x = rv.x*hv.x + (1.0f - rv.x)*c0;
        o.y = rv.y*hv.y + (1.0f - rv.y)*c1;
        o.z = rv.z*hv.z + (1.0f - rv.z)*c2;
        o.w = rv.w*hv.w + (1.0f - rv.w)*c3;
        *(float4*)&hbuf[hb] = o;
        unsigned long long hp, lp;
        split4(o, hp, lp);
        *(unsigned long long*)&hH[hb] = hp;
        *(unsigned long long*)&hL[hb] = lp;
        if (CIN == 2) {
            long sq = ((long)(b*TT + t))*NN*DOUT + (long)n*DOUT + tx*4;
            *(float4*)&g_seq0[sq] = o;
            *(unsigned long long*)&g_seqH[sq] = hp;
            *(unsigned long long*)&g_seqL[sq] = lp;
        } else {
            *(float4*)&curOut[((long)(b*TT + t))*NN*DOUT + (long)n*DOUT + tx*4] = o;
        }
        if (lastOut) *(float4*)&lastOut[hb] = o;
    }
}

// ---------------------------------------------------------------------------
// Host driver — graph-capturable. Streams: layer0 on sA, Gx on sC, layer1 on sB.
// ---------------------------------------------------------------------------
extern "C" void kernel_launch(void* const* d_in, const int* in_sizes, int n_in,
                              void* d_out, int out_size) {
    const float* x    = (const float*)d_in[0];
    const float* init = (const float*)d_in[1];
    const float* E    = (const float*)d_in[2];
    const float* adj  = (const float*)d_in[3];
    const float* wg0  = (const float*)d_in[4];
    const float* bg0  = (const float*)d_in[5];
    const float* wu0  = (const float*)d_in[6];
    const float* bu0  = (const float*)d_in[7];
    const float* wg1  = (const float*)d_in[8];
    const float* bg1  = (const float*)d_in[9];
    const float* wu1  = (const float*)d_in[10];
    const float* bu1  = (const float*)d_in[11];

    float* out      = (float*)d_out;
    float* lastBase = out + (long)CURSZ;

    static cudaStream_t sA = nullptr, sB = nullptr, sC = nullptr;
    static cudaEvent_t eFork = nullptr, eA = nullptr, eB = nullptr;
    static cudaEvent_t e0[TT], eC[TT];
    if (!sA) {
        cudaStreamCreateWithFlags(&sA, cudaStreamNonBlocking);
        cudaStreamCreateWithFlags(&sB, cudaStreamNonBlocking);
        cudaStreamCreateWithFlags(&sC, cudaStreamNonBlocking);
        cudaEventCreateWithFlags(&eFork, cudaEventDisableTiming);
        cudaEventCreateWithFlags(&eA, cudaEventDisableTiming);
        cudaEventCreateWithFlags(&eB, cudaEventDisableTiming);
        for (int t = 0; t < TT; t++) {
            cudaEventCreateWithFlags(&e0[t], cudaEventDisableTiming);
            cudaEventCreateWithFlags(&eC[t], cudaEventDisableTiming);
        }
    }

    // ---- prelude on the capture (default) stream ----
    prep_all<<<(unsigned)((C7 + 255) / 256), 256>>>(E, wg0, wu0, wg1, wu1,
                                                    bg0, bu0, bg1, bu1);
    prep_adjB<<<(NNP*NNP + 255) / 256, 256>>>(adj);
    init_h<<<(BND + 255) / 256, 256>>>(init, 0);
    init_h<<<(BND + 255) / 256, 256>>>(init, 1);
    graph_x2_all<<<dim3(5, BT/64), 256>>>(adj, x);

    cudaEventRecord(eFork, 0);
    cudaStreamWaitEvent(sA, eFork, 0);
    cudaStreamWaitEvent(sB, eFork, 0);
    cudaStreamWaitEvent(sC, eFork, 0);

    dim3 gGrid(5, BB);   // graph64_mma: 640 blocks x 256 thr

    // ---- layer 0 on sA ----
    for (int t = 0; t < TT; t++) {
        graph64_mma<<<gGrid, 256, 0, sA>>>(0, t, 0);                    // Gh0
        gate_k<2><<<dim3(NN,2), 256, 0, sA>>>(x, t);                    // z*h, r
        graph64_mma<<<gGrid, 256, 0, sA>>>(1, t, 1);                    // Gzh0
        cand_k<2><<<dim3(NN,2), 128, 0, sA>>>(x, t, nullptr,
                        (t == TT-1) ? lastBase : nullptr);              // h0', seq0[t]
        cudaEventRecord(e0[t], sA);
    }
    // ---- Gx producer on sC (gated on seq0[t], fully buffered per t) ----
    for (int t = 0; t < TT; t++) {
        cudaStreamWaitEvent(sC, e0[t], 0);
        graph64_mma<<<gGrid, 256, 0, sC>>>(2, t, 2);                    // Gxall[t]
        cudaEventRecord(eC[t], sC);
    }
    // ---- layer 1 on sB ----
    for (int t = 0; t < TT; t++) {
        graph64_mma<<<gGrid, 256, 0, sB>>>(3, t, 3);                    // Gh1
        cudaStreamWaitEvent(sB, eC[t], 0);                              // Gxall[t], seq0[t]
        gate_k<64><<<dim3(NN,2), 256, 0, sB>>>(nullptr, t);
        graph64_mma<<<gGrid, 256, 0, sB>>>(4, t, 4);                    // Gzh1
        cand_k<64><<<dim3(NN,2), 128, 0, sB>>>(nullptr, t, out,
                        (t == TT-1) ? lastBase + BND : nullptr);
    }

    cudaEventRecord(eA, sA);
    cudaEventRecord(eB, sB);
    cudaStreamWaitEvent(0, eA, 0);
    cudaStreamWaitEvent(0, eB, 0);
}

// round 13
// speedup vs baseline: 1.0323x; 1.0323x over previous
#include <cuda_runtime.h>
#include <cuda_bf16.h>
#include <math.h>
#include <cstdint>

// Problem constants
#define NN   307
#define TT   12
#define BB   128
#define DIN  2
#define DOUT 64
#define DE   10
#define NNP  320                  // padded node dim (k-dim for mma, mult of 16)

#define BND   (BB*NN*DOUT)        // 2,514,944
#define CURSZ (BB*TT*NN*DOUT)     // 30,179,328
#define BT    (BB*TT)             // 1536

// ---------------------------------------------------------------------------
// Device scratch
// ---------------------------------------------------------------------------
__device__ float g_Wg0[NN*132*128];
__device__ float g_Wu0[NN*132*64];
__device__ float g_Wg1[NN*256*128];
__device__ float g_Wu1[NN*256*64];
__device__ float g_bg0[NN*128];
__device__ float g_bu0[NN*64];
__device__ float g_bg1[NN*128];
__device__ float g_bu1[NN*64];

__device__ __nv_bfloat16 g_adjH[NNP*NNP];   // adj [n][m] bf16 hi plane, zero-padded
__device__ __nv_bfloat16 g_adjL[NNP*NNP];   // adj [n][m] bf16 lo plane

// per-layer state (layers run concurrently on separate streams)
__device__ float g_h0  [BND];
__device__ float g_zh0 [BND];
__device__ float g_r0  [BND];
__device__ float g_Gh0 [BND];
__device__ float g_Gzh0[BND];
__device__ float g_h1  [BND];
__device__ float g_zh1 [BND];
__device__ float g_r1  [BND];
__device__ float g_Gh1 [BND];
__device__ float g_Gzh1[BND];

__device__ float g_Gx2 [BT*NN*DIN];   // adj @ x (layer0, all t) [B,T,N,2]
__device__ float g_Gxall[CURSZ];      // adj @ seq0[t] for all t [B,T,N,64]
__device__ float g_seq0[CURSZ];       // layer0 output sequence [B,T,N,64]

// h-independent GEMM partials for layer1 (computed on sC)
__device__ float g_preg1[CURSZ*2];    // [B,T,N,128] gate partial
__device__ float g_preu1[CURSZ];      // [B,T,N,64]  cand partial

__device__ __forceinline__ float sigm(float v) { return 1.0f / (1.0f + expf(-v)); }

// packed fp32x2 helpers (GEMMs)
__device__ __forceinline__ unsigned long long pk2(float x, float y) {
    unsigned long long r;
    asm("mov.b64 %0, {%1, %2};" : "=l"(r) : "f"(x), "f"(y));
    return r;
}
__device__ __forceinline__ unsigned long long ffma2(unsigned long long a,
                                                    unsigned long long b,
                                                    unsigned long long c) {
    unsigned long long d;
    asm("fma.rn.f32x2 %0, %1, %2, %3;" : "=l"(d) : "l"(a), "l"(b), "l"(c));
    return d;
}
__device__ __forceinline__ void unpk2(unsigned long long v, float& lo, float& hi) {
    asm("mov.b64 {%0, %1}, %2;" : "=f"(lo), "=f"(hi) : "l"(v));
}

// bf16 mma.sync m16n8k16
__device__ __forceinline__ void mma_bf16(float* c, const uint32_t* a,
                                         uint32_t b0, uint32_t b1) {
    asm volatile(
        "mma.sync.aligned.m16n8k16.row.col.f32.bf16.bf16.f32 "
        "{%0,%1,%2,%3}, {%4,%5,%6,%7}, {%8,%9}, {%0,%1,%2,%3};"
        : "+f"(c[0]), "+f"(c[1]), "+f"(c[2]), "+f"(c[3])
        : "r"(a[0]), "r"(a[1]), "r"(a[2]), "r"(a[3]), "r"(b0), "r"(b1));
}

// ---------------------------------------------------------------------------
// prep kernels
// ---------------------------------------------------------------------------
#define S_WG0 (132*128)
#define S_WU0 (132*64)
#define S_WG1 (256*128)
#define S_WU1 (256*64)
#define C0 ((long)NN*S_WG0)
#define C1 (C0 + (long)NN*S_WU0)
#define C2 (C1 + (long)NN*S_WG1)
#define C3 (C2 + (long)NN*S_WU1)
#define C4 (C3 + (long)NN*128)
#define C5 (C4 + (long)NN*64)
#define C6 (C5 + (long)NN*128)
#define C7 (C6 + (long)NN*64)

__global__ void prep_all(const float* __restrict__ E,
                         const float* __restrict__ wg0, const float* __restrict__ wu0,
                         const float* __restrict__ wg1, const float* __restrict__ wu1,
                         const float* __restrict__ bg0, const float* __restrict__ bu0,
                         const float* __restrict__ bg1, const float* __restrict__ bu1) {
    long idx = (long)blockIdx.x * blockDim.x + threadIdx.x;
    if (idx >= C7) return;
    const float* pool; float* out; long loc; int S;
    if      (idx < C0) { pool = wg0; out = g_Wg0; loc = idx;      S = S_WG0; }
    else if (idx < C1) { pool = wu0; out = g_Wu0; loc = idx - C0; S = S_WU0; }
    else if (idx < C2) { pool = wg1; out = g_Wg1; loc = idx - C1; S = S_WG1; }
    else if (idx < C3) { pool = wu1; out = g_Wu1; loc = idx - C2; S = S_WU1; }
    else if (idx < C4) { pool = bg0; out = g_bg0; loc = idx - C3; S = 128;   }
    else if (idx < C5) { pool = bu0; out = g_bu0; loc = idx - C4; S = 64;    }
    else if (idx < C6) { pool = bg1; out = g_bg1; loc = idx - C5; S = 128;   }
    else               { pool = bu1; out = g_bu1; loc = idx - C6; S = 64;    }
    int n = (int)(loc / S);
    long j = loc - (long)n * S;
    float acc = 0.0f;
#pragma unroll
    for (int d = 0; d < DE; d++)
        acc += E[n*DE + d] * pool[(long)d*S + j];
    out[loc] = acc;
}

// adj -> bf16 hi/lo planes, [n][m] layout, zero-padded to 320x320
__global__ void prep_adjB(const float* __restrict__ adj) {
    int i = blockIdx.x * blockDim.x + threadIdx.x;
    if (i >= NNP*NNP) return;
    int n = i / NNP, m = i - n*NNP;
    float v = (n < NN && m < NN) ? adj[(long)n*NN + m] : 0.0f;
    __nv_bfloat16 h = __float2bfloat16(v);
    __nv_bfloat16 l = __float2bfloat16(v - __bfloat162float(h));
    g_adjH[i] = h;
    g_adjL[i] = l;
}

__global__ void init_h(const float* __restrict__ init, int l) {
    int i = blockIdx.x * blockDim.x + threadIdx.x;
    if (i < BND) {
        float v = init[(long)l*BND + i];
        if (l == 0) g_h0[i] = v; else g_h1[i] = v;
    }
}

// ---------------------------------------------------------------------------
// adj @ x for all timesteps (layer0, 2 channels): one launch, f32 (tiny)
// ---------------------------------------------------------------------------
__global__ void __launch_bounds__(256) graph_x2_all(const float* __restrict__ adj,
                                                    const float* __restrict__ x) {
    int n0  = blockIdx.x * 64;
    int bt0 = blockIdx.y * 64;
    int tid = threadIdx.x;
    int tx  = tid & 15;
    int ty  = tid >> 4;

    __shared__ float adjs[32][65];
    __shared__ float xs[64][65];

    float acc[4][4][2] = {};

    for (int m0 = 0; m0 < NN; m0 += 32) {
#pragma unroll
        for (int j = 0; j < 8; j++) {
            int lin = tid + j*256;
            int nl = lin >> 5, ml = lin & 31;
            int n = n0 + nl, m = m0 + ml;
            adjs[ml][nl] = (n < NN && m < NN) ? adj[(long)n*NN + m] : 0.0f;
        }
#pragma unroll
        for (int j = 0; j < 16; j++) {
            int lin = tid + j*256;
            int mc = lin & 63;
            int bt = lin >> 6;
            int m = m0 + (mc >> 1);
            xs[mc][bt] = (m < NN) ? x[((long)(bt0 + bt)*NN + m)*2 + (mc & 1)] : 0.0f;
        }
        __syncthreads();
#pragma unroll
        for (int ml = 0; ml < 32; ml++) {
            float a0 = adjs[ml][ty*4+0];
            float a1 = adjs[ml][ty*4+1];
            float a2 = adjs[ml][ty*4+2];
            float a3 = adjs[ml][ty*4+3];
#pragma unroll
            for (int jj = 0; jj < 4; jj++) {
                float x0 = xs[ml*2+0][tx*4+jj];
                float x1 = xs[ml*2+1][tx*4+jj];
                acc[0][jj][0] += a0*x0; acc[0][jj][1] += a0*x1;
                acc[1][jj][0] += a1*x0; acc[1][jj][1] += a1*x1;
                acc[2][jj][0] += a2*x0; acc[2][jj][1] += a2*x1;
                acc[3][jj][0] += a3*x0; acc[3][jj][1] += a3*x1;
            }
        }
        __syncthreads();
    }
#pragma unroll
    for (int i = 0; i < 4; i++) {
        int n = n0 + ty*4 + i;
        if (n >= NN) continue;
#pragma unroll
        for (int jj = 0; jj < 4; jj++) {
            int bt = bt0 + tx*4 + jj;
            *(float2*)&g_Gx2[((long)bt*NN + n)*2] =
                make_float2(acc[i][jj][0], acc[i][jj][1]);
        }
    }
}

// ---------------------------------------------------------------------------
// Graph propagation via bf16 split mma (R8/R11 version, 1 batch/block).
// Per block: 64 nodes x 64 channels x 1 batch; 8 warps as 4(m16) x 2(n32).
// grid (5, 128).  srcsel: 0=h0, 1=zh0, 2=seq0[t], 3=h1, 4=zh1
// dstsel: 0=Gh0, 1=Gzh0, 2=Gxall[t], 3=Gh1, 4=Gzh1
// ---------------------------------------------------------------------------
__global__ void __launch_bounds__(256) graph64_mma(int srcsel, int t, int dstsel) {
    const float* src; long sstride = (long)NN*DOUT;
    switch (srcsel) {
        case 0:  src = g_h0;  break;
        case 1:  src = g_zh0; break;
        case 2:  src = g_seq0 + (long)t*NN*DOUT; sstride = (long)TT*NN*DOUT; break;
        case 3:  src = g_h1;  break;
        default: src = g_zh1; break;
    }
    float* dst; long dstride = (long)NN*DOUT;
    switch (dstsel) {
        case 0:  dst = g_Gh0;  break;
        case 1:  dst = g_Gzh0; break;
        case 2:  dst = g_Gxall + (long)t*NN*DOUT; dstride = (long)TT*NN*DOUT; break;
        case 3:  dst = g_Gh1;  break;
        default: dst = g_Gzh1; break;
    }

    int n0  = blockIdx.x * 64;
    int b   = blockIdx.y;
    int tid = threadIdx.x;
    int lane = tid & 31;
    int wid  = tid >> 5;
    int wm = wid & 3;            // m16 tile: rows n0 + wm*16
    int wn = wid >> 2;           // n32 tile: cols wn*32

    __shared__ __nv_bfloat16 Ah[64][20], Al[64][20];   // A: [n][m16]
    __shared__ __nv_bfloat16 Bh[64][20], Bl[64][20];   // B: [c][m16]

    float acc[4][4];
#pragma unroll
    for (int i = 0; i < 4; i++)
#pragma unroll
        for (int j = 0; j < 4; j++) acc[i][j] = 0.0f;

    const float* sb = src + (long)b * sstride;
    int bc = tid & 63;           // B fill: channel
    int bm = (tid >> 6) * 4;     // B fill: first of 4 k rows

    for (int m0 = 0; m0 < NNP; m0 += 16) {
        // A fill: u32 = 2 bf16 per plane
#pragma unroll
        for (int j = 0; j < 2; j++) {
            int lin = tid + j*256;
            int nl = lin >> 3, kp = lin & 7;
            long src_off = (long)(n0 + nl)*NNP + m0 + kp*2;
            *(uint32_t*)&Ah[nl][kp*2] = *(const uint32_t*)&g_adjH[src_off];
            *(uint32_t*)&Al[nl][kp*2] = *(const uint32_t*)&g_adjL[src_off];
        }
        // B fill: 16k x 64c from f32 src, split into hi/lo
#pragma unroll
        for (int i = 0; i < 4; i++) {
            int ml = bm + i;
            int m  = m0 + ml;
            float v = (m < NN) ? sb[(long)m*DOUT + bc] : 0.0f;
            __nv_bfloat16 h = __float2bfloat16(v);
            __nv_bfloat16 l = __float2bfloat16(v - __bfloat162float(h));
            Bh[bc][ml] = h;
            Bl[bc][ml] = l;
        }
        __syncthreads();

        uint32_t a_h[4], a_l[4];
#pragma unroll
        for (int j = 0; j < 4; j++) {
            int row = wm*16 + (lane >> 2) + (j & 1)*8;
            int kp  = (lane & 3)*2 + (j & 2)*4;
            a_h[j] = *(const uint32_t*)&Ah[row][kp];
            a_l[j] = *(const uint32_t*)&Al[row][kp];
        }
#pragma unroll
        for (int tn = 0; tn < 4; tn++) {
            int cc  = wn*32 + tn*8 + (lane >> 2);
            int k0p = (lane & 3)*2;
            uint32_t b_h0 = *(const uint32_t*)&Bh[cc][k0p];
            uint32_t b_h1 = *(const uint32_t*)&Bh[cc][k0p + 8];
            uint32_t b_l0 = *(const uint32_t*)&Bl[cc][k0p];
            uint32_t b_l1 = *(const uint32_t*)&Bl[cc][k0p + 8];
            mma_bf16(acc[tn], a_h, b_h0, b_h1);
            mma_bf16(acc[tn], a_h, b_l0, b_l1);
            mma_bf16(acc[tn], a_l, b_h0, b_h1);
        }
        __syncthreads();
    }

    long db = (long)b * dstride;
#pragma unroll
    for (int tn = 0; tn < 4; tn++) {
        int n = n0 + wm*16 + (lane >> 2);
        int c = wn*32 + tn*8 + (lane & 3)*2;
        if (n < NN)
            *(float2*)&dst[db + (long)n*DOUT + c] =
                make_float2(acc[tn][0], acc[tn][1]);
        if (n + 8 < NN)
            *(float2*)&dst[db + (long)(n + 8)*DOUT + c] =
                make_float2(acc[tn][2], acc[tn][3]);
    }
}

// ---------------------------------------------------------------------------
// A-row gather: A[b, kk] = [ x(CIN) | h_or_zh(64) | Gx(CIN) | Gh_or_Gzh(64) ]
// ---------------------------------------------------------------------------
template<int CIN, int MODE>
__device__ __forceinline__ float gatherA(const float* __restrict__ xext,
                                         int b, int n, int t, int kk) {
    long hoff = ((long)b*NN + n)*64;
    if (CIN == 2) {
        if (kk >= 132) return 0.0f;
        long xoff = ((long)b*TT + t)*NN*2 + (long)n*2;
        if (kk < 2)   return xext[xoff + kk];
        if (kk < 66)  return (MODE ? g_zh0 : g_h0)[hoff + (kk - 2)];
        if (kk < 68)  return g_Gx2[xoff + (kk - 66)];
        return (MODE ? g_Gzh0 : g_Gh0)[hoff + (kk - 68)];
    } else {
        long xoff = ((long)b*TT + t)*NN*64 + (long)n*64;
        if (kk < 64)  return g_seq0[xoff + kk];
        if (kk < 128) return (MODE ? g_zh1 : g_h1)[hoff + (kk - 64)];
        if (kk < 192) return g_Gxall[xoff + (kk - 128)];
        return (MODE ? g_Gzh1 : g_Gh1)[hoff + (kk - 192)];
    }
}

// ---------------------------------------------------------------------------
// pre1_k: h-independent GEMM partials for layer1 (k-tiles {0,1,4,5}).
// grid (NN, 2bh, 3): z=0 gate o[0:64), z=1 gate o[64:128), z=2 cand o[0:64).
// 128 threads, 64b x 64o tile.
// ---------------------------------------------------------------------------
__global__ void __launch_bounds__(128, 8) pre1_k(int t) {
    int z  = blockIdx.z;
    const float* W = (z < 2) ? g_Wg1 : g_Wu1;
    int CO = (z < 2) ? 128 : 64;
    int oc0 = (z == 1) ? 64 : 0;

    int n  = blockIdx.x;
    int bh = blockIdx.y;
    int tid = threadIdx.x;
    int tx = tid & 15;
    int ty = tid >> 4;

    __shared__ float As[32][68];
    __shared__ float Ws[32][68];

    unsigned long long acc2[8][2];
#pragma unroll
    for (int i = 0; i < 8; i++) { acc2[i][0] = 0ull; acc2[i][1] = 0ull; }

    const int kts[4] = {0, 1, 4, 5};
#pragma unroll
    for (int kt = 0; kt < 4; kt++) {
        int k0 = kts[kt] * 32;
#pragma unroll
        for (int j = 0; j < 16; j++) {
            int lin = tid + j*128;
            int kl = lin & 31;
            int b  = lin >> 5;
            As[kl][b] = gatherA<64,0>(nullptr, bh*64 + b, n, t, k0 + kl);
        }
#pragma unroll
        for (int j = 0; j < 4; j++) {
            int lin = tid + j*128;
            int c4  = lin & 15;
            int row = lin >> 4;
            int kk = k0 + row;
            float4 v = *(const float4*)&W[((long)n*256 + kk)*CO + oc0 + c4*4];
            *(float4*)&Ws[row][c4*4] = v;
        }
        __syncthreads();
#pragma unroll
        for (int k = 0; k < 32; k++) {
            float4 aLo = *(const float4*)&As[k][ty*8];
            float4 aHi = *(const float4*)&As[k][ty*8 + 4];
            ulonglong2 w2 = *(const ulonglong2*)&Ws[k][tx*4];
            float av[8] = {aLo.x, aLo.y, aLo.z, aLo.w,
                           aHi.x, aHi.y, aHi.z, aHi.w};
#pragma unroll
            for (int i = 0; i < 8; i++) {
                unsigned long long ad = pk2(av[i], av[i]);
                acc2[i][0] = ffma2(ad, w2.x, acc2[i][0]);
                acc2[i][1] = ffma2(ad, w2.y, acc2[i][1]);
            }
        }
        __syncthreads();
    }

#pragma unroll
    for (int i = 0; i < 8; i++) {
        int b = bh*64 + ty*8 + i;
        float v0, v1, v2, v3;
        unpk2(acc2[i][0], v0, v1);
        unpk2(acc2[i][1], v2, v3);
        long base = ((long)(b*TT + t)*NN + n);
        if (z < 2)
            *(float4*)&g_preg1[base*128 + oc0 + tx*4] = make_float4(v0, v1, v2, v3);
        else
            *(float4*)&g_preu1[base*64 + tx*4] = make_float4(v0, v1, v2, v3);
    }
}

// ---------------------------------------------------------------------------
// Gate GEMM, oh-merged: tile 64b x 128o, 256 threads, 8b x 4o per thread.
// CIN==64: only h-dependent k-tiles {2,3,6,7}; adds pre partial in epilogue.
// ---------------------------------------------------------------------------
template<int CIN>
__global__ void __launch_bounds__(256, 4) gate_k(const float* __restrict__ xext, int t) {
    constexpr int KD  = 2*CIN + 2*DOUT;
    constexpr int NKT = (CIN == 2) ? 5 : 4;
    const float* W    = (CIN == 2) ? g_Wg0 : g_Wg1;
    const float* bias = (CIN == 2) ? g_bg0 : g_bg1;
    const float* hbuf = (CIN == 2) ? g_h0  : g_h1;
    float* zhbuf      = (CIN == 2) ? g_zh0 : g_zh1;
    float* rbuf       = (CIN == 2) ? g_r0  : g_r1;

    int n  = blockIdx.x;
    int bh = blockIdx.y;
    int tid = threadIdx.x;
    int tx = tid & 31;          // o group (4 cols, 32 groups = 128 o)
    int ty = tid >> 5;          // b group (8 rows)

    __shared__ float As[32][68];    // [kk][b]
    __shared__ float Ws[32][132];   // [kk][o]

    unsigned long long acc2[8][2];
#pragma unroll
    for (int i = 0; i < 8; i++) { acc2[i][0] = 0ull; acc2[i][1] = 0ull; }

    const int kts1[4] = {2, 3, 6, 7};
    for (int kt = 0; kt < NKT; kt++) {
        int k0 = (CIN == 2) ? kt*32 : kts1[kt]*32;
#pragma unroll
        for (int j = 0; j < 8; j++) {
            int lin = tid + j*256;
            int kl = lin & 31;
            int b  = lin >> 5;
            As[kl][b] = gatherA<CIN,0>(xext, bh*64 + b, n, t, k0 + kl);
        }
#pragma unroll
        for (int j = 0; j < 4; j++) {
            int lin = tid + j*256;
            int c4  = lin & 31;
            int row = lin >> 5;
            int kk = k0 + row;
            float4 v = make_float4(0.f, 0.f, 0.f, 0.f);
            if (kk < KD)
                v = *(const float4*)&W[((long)n*KD + kk)*128 + c4*4];
            *(float4*)&Ws[row][c4*4] = v;
        }
        __syncthreads();
#pragma unroll
        for (int k = 0; k < 32; k++) {
            float4 aLo = *(const float4*)&As[k][ty*8];
            float4 aHi = *(const float4*)&As[k][ty*8 + 4];
            ulonglong2 w2 = *(const ulonglong2*)&Ws[k][tx*4];
            float av[8] = {aLo.x, aLo.y, aLo.z, aLo.w,
                           aHi.x, aHi.y, aHi.z, aHi.w};
#pragma unroll
            for (int i = 0; i < 8; i++) {
                unsigned long long ad = pk2(av[i], av[i]);
                acc2[i][0] = ffma2(ad, w2.x, acc2[i][0]);
                acc2[i][1] = ffma2(ad, w2.y, acc2[i][1]);
            }
        }
        __syncthreads();
    }

    int o0 = tx*4;
    float4 bv = *(const float4*)&bias[n*128 + o0];
    bool isZ = (o0 < 64);
    int oc = isZ ? o0 : (o0 - 64);
#pragma unroll
    for (int i = 0; i < 8; i++) {
        int b = bh*64 + ty*8 + i;
        long hb = ((long)b*NN + n)*64 + oc;
        float v0, v1, v2, v3;
        unpk2(acc2[i][0], v0, v1);
        unpk2(acc2[i][1], v2, v3);
        if (CIN == 64) {
            float4 pv = *(const float4*)
                &g_preg1[((long)(b*TT + t)*NN + n)*128 + o0];
            v0 += pv.x; v1 += pv.y; v2 += pv.z; v3 += pv.w;
        }
        v0 = sigm(v0 + bv.x); v1 = sigm(v1 + bv.y);
        v2 = sigm(v2 + bv.z); v3 = sigm(v3 + bv.w);
        if (isZ) {
            float4 hv = *(const float4*)&hbuf[hb];
            *(float4*)&zhbuf[hb] = make_float4(v0*hv.x, v1*hv.y, v2*hv.z, v3*hv.w);
        } else {
            *(float4*)&rbuf[hb] = make_float4(v0, v1, v2, v3);
        }
    }
}

// ---------------------------------------------------------------------------
// Candidate GEMM + GRU update. CIN==64: k-tiles {2,3,6,7} + pre partial.
// tile 64b x 64o, grid (NN, 2).
// ---------------------------------------------------------------------------
template<int CIN>
__global__ void __launch_bounds__(128, 8) cand_k(const float* __restrict__ xext, int t,
                                                 float* __restrict__ curOut,
                                                 float* __restrict__ lastOut) {
    constexpr int KD  = 2*CIN + 2*DOUT;
    constexpr int NKT = (CIN == 2) ? 5 : 4;
    const float* W    = (CIN == 2) ? g_Wu0 : g_Wu1;
    const float* bias = (CIN == 2) ? g_bu0 : g_bu1;
    float* hbuf       = (CIN == 2) ? g_h0  : g_h1;
    const float* rbuf = (CIN == 2) ? g_r0  : g_r1;

    int n  = blockIdx.x;
    int bh = blockIdx.y;
    int tid = threadIdx.x;
    int tx = tid & 15;
    int ty = tid >> 4;

    __shared__ float As[32][68];
    __shared__ float Ws[32][68];

    unsigned long long acc2[8][2];
#pragma unroll
    for (int i = 0; i < 8; i++) { acc2[i][0] = 0ull; acc2[i][1] = 0ull; }

    const int kts1[4] = {2, 3, 6, 7};
    for (int kt = 0; kt < NKT; kt++) {
        int k0 = (CIN == 2) ? kt*32 : kts1[kt]*32;
#pragma unroll
        for (int j = 0; j < 16; j++) {
            int lin = tid + j*128;
            int kl = lin & 31;
            int b  = lin >> 5;
            As[kl][b] = gatherA<CIN,1>(xext, bh*64 + b, n, t, k0 + kl);
        }
#pragma unroll
        for (int j = 0; j < 4; j++) {
            int lin = tid + j*128;
            int c4  = lin & 15;
            int row = lin >> 4;
            int kk = k0 + row;
            float4 v = make_float4(0.f, 0.f, 0.f, 0.f);
            if (kk < KD)
                v = *(const float4*)&W[((long)n*KD + kk)*64 + c4*4];
            *(float4*)&Ws[row][c4*4] = v;
        }
        __syncthreads();
#pragma unroll
        for (int k = 0; k < 32; k++) {
            float4 aLo = *(const float4*)&As[k][ty*8];
            float4 aHi = *(const float4*)&As[k][ty*8 + 4];
            ulonglong2 w2 = *(const ulonglong2*)&Ws[k][tx*4];
            float av[8] = {aLo.x, aLo.y, aLo.z, aLo.w,
                           aHi.x, aHi.y, aHi.z, aHi.w};
#pragma unroll
            for (int i = 0; i < 8; i++) {
                unsigned long long ad = pk2(av[i], av[i]);
                acc2[i][0] = ffma2(ad, w2.x, acc2[i][0]);
                acc2[i][1] = ffma2(ad, w2.y, acc2[i][1]);
            }
        }
        __syncthreads();
    }

    float4 bv = *(const float4*)&bias[n*64 + tx*4];
#pragma unroll
    for (int i = 0; i < 8; i++) {
        int b = bh*64 + ty*8 + i;
        long hb = ((long)b*NN + n)*64 + tx*4;
        float c0, c1, c2, c3;
        unpk2(acc2[i][0], c0, c1);
        unpk2(acc2[i][1], c2, c3);
        if (CIN == 64) {
            float4 pv = *(const float4*)
                &g_preu1[((long)(b*TT + t)*NN + n)*64 + tx*4];
            c0 += pv.x; c1 += pv.y; c2 += pv.z; c3 += pv.w;
        }
        c0 = tanhf(c0 + bv.x); c1 = tanhf(c1 + bv.y);
        c2 = tanhf(c2 + bv.z); c3 = tanhf(c3 + bv.w);
        float4 rv = *(const float4*)&rbuf[hb];
        float4 hv = *(const float4*)&hbuf[hb];
        float4 o;
        o.x = rv.x*hv.x + (1.0f - rv.x)*c0;
        o.y = rv.y*hv.y + (1.0f - rv.y)*c1;
        o.z = rv.z*hv.z + (1.0f - rv.z)*c2;
        o.w = rv.w*hv.w + (1.0f - rv.w)*c3;
        *(float4*)&hbuf[hb] = o;
        float* seq = (CIN == 2) ? g_seq0 : curOut;
        *(float4*)&seq[((long)(b*TT + t))*NN*DOUT + (long)n*DOUT + tx*4] = o;
        if (lastOut) *(float4*)&lastOut[hb] = o;
    }
}

// ---------------------------------------------------------------------------
// Host driver — graph-capturable. Streams: layer0 on sA, Gx+pre on sC,
// layer1 on sB.
// ---------------------------------------------------------------------------
extern "C" void kernel_launch(void* const* d_in, const int* in_sizes, int n_in,
                              void* d_out, int out_size) {
    const float* x    = (const float*)d_in[0];
    const float* init = (const float*)d_in[1];
    const float* E    = (const float*)d_in[2];
    const float* adj  = (const float*)d_in[3];
    const float* wg0  = (const float*)d_in[4];
    const float* bg0  = (const float*)d_in[5];
    const float* wu0  = (const float*)d_in[6];
    const float* bu0  = (const float*)d_in[7];
    const float* wg1  = (const float*)d_in[8];
    const float* bg1  = (const float*)d_in[9];
    const float* wu1  = (const float*)d_in[10];
    const float* bu1  = (const float*)d_in[11];

    float* out      = (float*)d_out;
    float* lastBase = out + (long)CURSZ;

    static cudaStream_t sA = nullptr, sB = nullptr, sC = nullptr;
    static cudaEvent_t eFork = nullptr, eA = nullptr, eB = nullptr;
    static cudaEvent_t e0[TT], eC[TT];
    if (!sA) {
        cudaStreamCreateWithFlags(&sA, cudaStreamNonBlocking);
        cudaStreamCreateWithFlags(&sB, cudaStreamNonBlocking);
        cudaStreamCreateWithFlags(&sC, cudaStreamNonBlocking);
        cudaEventCreateWithFlags(&eFork, cudaEventDisableTiming);
        cudaEventCreateWithFlags(&eA, cudaEventDisableTiming);
        cudaEventCreateWithFlags(&eB, cudaEventDisableTiming);
        for (int t = 0; t < TT; t++) {
            cudaEventCreateWithFlags(&e0[t], cudaEventDisableTiming);
            cudaEventCreateWithFlags(&eC[t], cudaEventDisableTiming);
        }
    }

    // ---- prelude on the capture (default) stream ----
    prep_all<<<(unsigned)((C7 + 255) / 256), 256>>>(E, wg0, wu0, wg1, wu1,
                                                    bg0, bu0, bg1, bu1);
    prep_adjB<<<(NNP*NNP + 255) / 256, 256>>>(adj);
    init_h<<<(BND + 255) / 256, 256>>>(init, 0);
    init_h<<<(BND + 255) / 256, 256>>>(init, 1);
    graph_x2_all<<<dim3(5, BT/64), 256>>>(adj, x);

    cudaEventRecord(eFork, 0);
    cudaStreamWaitEvent(sA, eFork, 0);
    cudaStreamWaitEvent(sB, eFork, 0);
    cudaStreamWaitEvent(sC, eFork, 0);

    dim3 gGrid(5, BB);   // graph64_mma: 640 blocks x 256 thr

    // ---- layer 0 on sA ----
    for (int t = 0; t < TT; t++) {
        graph64_mma<<<gGrid, 256, 0, sA>>>(0, t, 0);                    // Gh0
        gate_k<2><<<dim3(NN,2), 256, 0, sA>>>(x, t);                    // z*h, r
        graph64_mma<<<gGrid, 256, 0, sA>>>(1, t, 1);                    // Gzh0
        cand_k<2><<<dim3(NN,2), 128, 0, sA>>>(x, t, nullptr,
                        (t == TT-1) ? lastBase : nullptr);              // h0', seq0[t]
        cudaEventRecord(e0[t], sA);
    }
    // ---- Gx + h-independent partials on sC ----
    for (int t = 0; t < TT; t++) {
        cudaStreamWaitEvent(sC, e0[t], 0);
        graph64_mma<<<gGrid, 256, 0, sC>>>(2, t, 2);                    // Gxall[t]
        pre1_k<<<dim3(NN, 2, 3), 128, 0, sC>>>(t);                      // preg1/preu1[t]
        cudaEventRecord(eC[t], sC);
    }
    // ---- layer 1 on sB ----
    for (int t = 0; t < TT; t++) {
        graph64_mma<<<gGrid, 256, 0, sB>>>(3, t, 3);                    // Gh1
        cudaStreamWaitEvent(sB, eC[t], 0);                              // pre[t], Gxall[t]
        gate_k<64><<<dim3(NN,2), 256, 0, sB>>>(nullptr, t);             // K=128 + pre
        graph64_mma<<<gGrid, 256, 0, sB>>>(4, t, 4);                    // Gzh1
        cand_k<64><<<dim3(NN,2), 128, 0, sB>>>(nullptr, t, out,
                        (t == TT-1) ? lastBase + BND : nullptr);        // K=128 + pre
    }

    cudaEventRecord(eA, sA);
    cudaEventRecord(eB, sB);
    cudaStreamWaitEvent(0, eA, 0);
    cudaStreamWaitEvent(0, eB, 0);
}

// round 14
// speedup vs baseline: 1.1083x; 1.0737x over previous
#include <cuda_runtime.h>
#include <cuda_bf16.h>
#include <math.h>
#include <cstdint>

// Problem constants
#define NN   307
#define TT   12
#define BB   128
#define DIN  2
#define DOUT 64
#define DE   10
#define NNP  320                  // padded node dim (k-dim for mma, mult of 32)

#define BND   (BB*NN*DOUT)        // 2,514,944
#define CURSZ (BB*TT*NN*DOUT)     // 30,179,328
#define BT    (BB*TT)             // 1536

// ---------------------------------------------------------------------------
// Device scratch
// ---------------------------------------------------------------------------
__device__ float g_Wg0[NN*132*128];
__device__ float g_Wu0[NN*132*64];
__device__ float g_Wg1[NN*256*128];
__device__ float g_Wu1[NN*256*64];
__device__ float g_bg0[NN*128];
__device__ float g_bu0[NN*64];
__device__ float g_bg1[NN*128];
__device__ float g_bu1[NN*64];

__device__ __nv_bfloat16 g_adjH[NNP*NNP];   // adj [n][m] bf16 hi plane, zero-padded
__device__ __nv_bfloat16 g_adjL[NNP*NNP];   // adj [n][m] bf16 lo plane

// per-layer state (layers run concurrently on separate streams)
__device__ float g_h0  [BND];
__device__ float g_zh0 [BND];
__device__ float g_r0  [BND];
__device__ float g_Gh0 [BND];
__device__ float g_Gzh0[BND];
__device__ float g_h1  [BND];
__device__ float g_zh1 [BND];
__device__ float g_r1  [BND];
__device__ float g_Gh1 [BND];
__device__ float g_Gzh1[BND];

__device__ float g_Gx2 [BT*NN*DIN];   // adj @ x (layer0, all t) [B,T,N,2]
__device__ float g_Gxall[CURSZ];      // adj @ seq0[t] for all t [B,T,N,64]
__device__ float g_seq0[CURSZ];       // layer0 output sequence [B,T,N,64]

// h-independent GEMM partials for layer1 (computed on sC)
__device__ float g_preg1[CURSZ*2];    // [B,T,N,128] gate partial
__device__ float g_preu1[CURSZ];      // [B,T,N,64]  cand partial

__device__ __forceinline__ float sigm(float v) { return 1.0f / (1.0f + expf(-v)); }

// packed fp32x2 helpers (GEMMs)
__device__ __forceinline__ unsigned long long pk2(float x, float y) {
    unsigned long long r;
    asm("mov.b64 %0, {%1, %2};" : "=l"(r) : "f"(x), "f"(y));
    return r;
}
__device__ __forceinline__ unsigned long long ffma2(unsigned long long a,
                                                    unsigned long long b,
                                                    unsigned long long c) {
    unsigned long long d;
    asm("fma.rn.f32x2 %0, %1, %2, %3;" : "=l"(d) : "l"(a), "l"(b), "l"(c));
    return d;
}
__device__ __forceinline__ void unpk2(unsigned long long v, float& lo, float& hi) {
    asm("mov.b64 {%0, %1}, %2;" : "=f"(lo), "=f"(hi) : "l"(v));
}

// bf16 mma.sync m16n8k16
__device__ __forceinline__ void mma_bf16(float* c, const uint32_t* a,
                                         uint32_t b0, uint32_t b1) {
    asm volatile(
        "mma.sync.aligned.m16n8k16.row.col.f32.bf16.bf16.f32 "
        "{%0,%1,%2,%3}, {%4,%5,%6,%7}, {%8,%9}, {%0,%1,%2,%3};"
        : "+f"(c[0]), "+f"(c[1]), "+f"(c[2]), "+f"(c[3])
        : "r"(a[0]), "r"(a[1]), "r"(a[2]), "r"(a[3]), "r"(b0), "r"(b1));
}

// ---------------------------------------------------------------------------
// prep kernels
// ---------------------------------------------------------------------------
#define S_WG0 (132*128)
#define S_WU0 (132*64)
#define S_WG1 (256*128)
#define S_WU1 (256*64)
#define C0 ((long)NN*S_WG0)
#define C1 (C0 + (long)NN*S_WU0)
#define C2 (C1 + (long)NN*S_WG1)
#define C3 (C2 + (long)NN*S_WU1)
#define C4 (C3 + (long)NN*128)
#define C5 (C4 + (long)NN*64)
#define C6 (C5 + (long)NN*128)
#define C7 (C6 + (long)NN*64)

__global__ void prep_all(const float* __restrict__ E,
                         const float* __restrict__ wg0, const float* __restrict__ wu0,
                         const float* __restrict__ wg1, const float* __restrict__ wu1,
                         const float* __restrict__ bg0, const float* __restrict__ bu0,
                         const float* __restrict__ bg1, const float* __restrict__ bu1) {
    long idx = (long)blockIdx.x * blockDim.x + threadIdx.x;
    if (idx >= C7) return;
    const float* pool; float* out; long loc; int S;
    if      (idx < C0) { pool = wg0; out = g_Wg0; loc = idx;      S = S_WG0; }
    else if (idx < C1) { pool = wu0; out = g_Wu0; loc = idx - C0; S = S_WU0; }
    else if (idx < C2) { pool = wg1; out = g_Wg1; loc = idx - C1; S = S_WG1; }
    else if (idx < C3) { pool = wu1; out = g_Wu1; loc = idx - C2; S = S_WU1; }
    else if (idx < C4) { pool = bg0; out = g_bg0; loc = idx - C3; S = 128;   }
    else if (idx < C5) { pool = bu0; out = g_bu0; loc = idx - C4; S = 64;    }
    else if (idx < C6) { pool = bg1; out = g_bg1; loc = idx - C5; S = 128;   }
    else               { pool = bu1; out = g_bu1; loc = idx - C6; S = 64;    }
    int n = (int)(loc / S);
    long j = loc - (long)n * S;
    float acc = 0.0f;
#pragma unroll
    for (int d = 0; d < DE; d++)
        acc += E[n*DE + d] * pool[(long)d*S + j];
    out[loc] = acc;
}

// adj -> bf16 hi/lo planes, [n][m] layout, zero-padded to 320x320
__global__ void prep_adjB(const float* __restrict__ adj) {
    int i = blockIdx.x * blockDim.x + threadIdx.x;
    if (i >= NNP*NNP) return;
    int n = i / NNP, m = i - n*NNP;
    float v = (n < NN && m < NN) ? adj[(long)n*NN + m] : 0.0f;
    __nv_bfloat16 h = __float2bfloat16(v);
    __nv_bfloat16 l = __float2bfloat16(v - __bfloat162float(h));
    g_adjH[i] = h;
    g_adjL[i] = l;
}

// both layers in one launch (grid.y = layer)
__global__ void init_h(const float* __restrict__ init) {
    int l = blockIdx.y;
    int i = blockIdx.x * blockDim.x + threadIdx.x;
    if (i < BND) {
        float v = init[(long)l*BND + i];
        if (l == 0) g_h0[i] = v; else g_h1[i] = v;
    }
}

// ---------------------------------------------------------------------------
// adj @ x for all timesteps (layer0, 2 channels): one launch, f32 (tiny)
// ---------------------------------------------------------------------------
__global__ void __launch_bounds__(256) graph_x2_all(const float* __restrict__ adj,
                                                    const float* __restrict__ x) {
    int n0  = blockIdx.x * 64;
    int bt0 = blockIdx.y * 64;
    int tid = threadIdx.x;
    int tx  = tid & 15;
    int ty  = tid >> 4;

    __shared__ float adjs[32][65];
    __shared__ float xs[64][65];

    float acc[4][4][2] = {};

    for (int m0 = 0; m0 < NN; m0 += 32) {
#pragma unroll
        for (int j = 0; j < 8; j++) {
            int lin = tid + j*256;
            int nl = lin >> 5, ml = lin & 31;
            int n = n0 + nl, m = m0 + ml;
            adjs[ml][nl] = (n < NN && m < NN) ? adj[(long)n*NN + m] : 0.0f;
        }
#pragma unroll
        for (int j = 0; j < 16; j++) {
            int lin = tid + j*256;
            int mc = lin & 63;
            int bt = lin >> 6;
            int m = m0 + (mc >> 1);
            xs[mc][bt] = (m < NN) ? x[((long)(bt0 + bt)*NN + m)*2 + (mc & 1)] : 0.0f;
        }
        __syncthreads();
#pragma unroll
        for (int ml = 0; ml < 32; ml++) {
            float a0 = adjs[ml][ty*4+0];
            float a1 = adjs[ml][ty*4+1];
            float a2 = adjs[ml][ty*4+2];
            float a3 = adjs[ml][ty*4+3];
#pragma unroll
            for (int jj = 0; jj < 4; jj++) {
                float x0 = xs[ml*2+0][tx*4+jj];
                float x1 = xs[ml*2+1][tx*4+jj];
                acc[0][jj][0] += a0*x0; acc[0][jj][1] += a0*x1;
                acc[1][jj][0] += a1*x0; acc[1][jj][1] += a1*x1;
                acc[2][jj][0] += a2*x0; acc[2][jj][1] += a2*x1;
                acc[3][jj][0] += a3*x0; acc[3][jj][1] += a3*x1;
            }
        }
        __syncthreads();
    }
#pragma unroll
    for (int i = 0; i < 4; i++) {
        int n = n0 + ty*4 + i;
        if (n >= NN) continue;
#pragma unroll
        for (int jj = 0; jj < 4; jj++) {
            int bt = bt0 + tx*4 + jj;
            *(float2*)&g_Gx2[((long)bt*NN + n)*2] =
                make_float2(acc[i][jj][0], acc[i][jj][1]);
        }
    }
}

// ---------------------------------------------------------------------------
// Graph propagation via bf16 split mma, k-chunk 32 (halved barrier count).
// Per block: 64n x 64c x 1b; 8 warps as 4(m16) x 2(n32). grid (5, 128).
// Rows padded to 40 halves (80B): 20-word row stride -> conflict-free frags.
// srcsel: 0=h0, 1=zh0, 2=seq0[t], 3=h1, 4=zh1
// dstsel: 0=Gh0, 1=Gzh0, 2=Gxall[t], 3=Gh1, 4=Gzh1
// ---------------------------------------------------------------------------
__global__ void __launch_bounds__(256) graph64_mma(int srcsel, int t, int dstsel) {
    const float* src; long sstride = (long)NN*DOUT;
    switch (srcsel) {
        case 0:  src = g_h0;  break;
        case 1:  src = g_zh0; break;
        case 2:  src = g_seq0 + (long)t*NN*DOUT; sstride = (long)TT*NN*DOUT; break;
        case 3:  src = g_h1;  break;
        default: src = g_zh1; break;
    }
    float* dst; long dstride = (long)NN*DOUT;
    switch (dstsel) {
        case 0:  dst = g_Gh0;  break;
        case 1:  dst = g_Gzh0; break;
        case 2:  dst = g_Gxall + (long)t*NN*DOUT; dstride = (long)TT*NN*DOUT; break;
        case 3:  dst = g_Gh1;  break;
        default: dst = g_Gzh1; break;
    }

    int n0  = blockIdx.x * 64;
    int b   = blockIdx.y;
    int tid = threadIdx.x;
    int lane = tid & 31;
    int wid  = tid >> 5;
    int wm = wid & 3;            // m16 tile: rows n0 + wm*16
    int wn = wid >> 2;           // n32 tile: cols wn*32

    __shared__ __nv_bfloat16 Ah[64][40], Al[64][40];   // A: [n][32k pad 40]
    __shared__ __nv_bfloat16 Bh[64][40], Bl[64][40];   // B: [c][32k pad 40]

    float acc[4][4];
#pragma unroll
    for (int i = 0; i < 4; i++)
#pragma unroll
        for (int j = 0; j < 4; j++) acc[i][j] = 0.0f;

    const float* sb = src + (long)b * sstride;
    int bc = tid & 63;           // B fill: channel
    int bm = (tid >> 6) * 8;     // B fill: first of 8 k rows

    for (int m0 = 0; m0 < NNP; m0 += 32) {
        // A fill: 64 rows x 16 u32 per plane = 1024; 4 per thread per plane
#pragma unroll
        for (int j = 0; j < 4; j++) {
            int lin = tid + j*256;
            int nl = lin >> 4, kp = lin & 15;
            long src_off = (long)(n0 + nl)*NNP + m0 + kp*2;
            *(uint32_t*)&Ah[nl][kp*2] = *(const uint32_t*)&g_adjH[src_off];
            *(uint32_t*)&Al[nl][kp*2] = *(const uint32_t*)&g_adjL[src_off];
        }
        // B fill: 32k x 64c from f32 src, split into hi/lo
#pragma unroll
        for (int i = 0; i < 8; i++) {
            int ml = bm + i;
            int m  = m0 + ml;
            float v = (m < NN) ? sb[(long)m*DOUT + bc] : 0.0f;
            __nv_bfloat16 h = __float2bfloat16(v);
            __nv_bfloat16 l = __float2bfloat16(v - __bfloat162float(h));
            Bh[bc][ml] = h;
            Bl[bc][ml] = l;
        }
        __syncthreads();

#pragma unroll
        for (int ks = 0; ks < 2; ks++) {
            int kb = ks * 16;
            uint32_t a_h[4], a_l[4];
#pragma unroll
            for (int j = 0; j < 4; j++) {
                int row = wm*16 + (lane >> 2) + (j & 1)*8;
                int kp  = kb + (lane & 3)*2 + (j & 2)*4;
                a_h[j] = *(const uint32_t*)&Ah[row][kp];
                a_l[j] = *(const uint32_t*)&Al[row][kp];
            }
#pragma unroll
            for (int tn = 0; tn < 4; tn++) {
                int cc  = wn*32 + tn*8 + (lane >> 2);
                int k0p = kb + (lane & 3)*2;
                uint32_t b_h0 = *(const uint32_t*)&Bh[cc][k0p];
                uint32_t b_h1 = *(const uint32_t*)&Bh[cc][k0p + 8];
                uint32_t b_l0 = *(const uint32_t*)&Bl[cc][k0p];
                uint32_t b_l1 = *(const uint32_t*)&Bl[cc][k0p + 8];
                mma_bf16(acc[tn], a_h, b_h0, b_h1);
                mma_bf16(acc[tn], a_h, b_l0, b_l1);
                mma_bf16(acc[tn], a_l, b_h0, b_h1);
            }
        }
        __syncthreads();
    }

    long db = (long)b * dstride;
#pragma unroll
    for (int tn = 0; tn < 4; tn++) {
        int n = n0 + wm*16 + (lane >> 2);
        int c = wn*32 + tn*8 + (lane & 3)*2;
        if (n < NN)
            *(float2*)&dst[db + (long)n*DOUT + c] =
                make_float2(acc[tn][0], acc[tn][1]);
        if (n + 8 < NN)
            *(float2*)&dst[db + (long)(n + 8)*DOUT + c] =
                make_float2(acc[tn][2], acc[tn][3]);
    }
}

// ---------------------------------------------------------------------------
// A-row gather: A[b, kk] = [ x(CIN) | h_or_zh(64) | Gx(CIN) | Gh_or_Gzh(64) ]
// ---------------------------------------------------------------------------
template<int CIN, int MODE>
__device__ __forceinline__ float gatherA(const float* __restrict__ xext,
                                         int b, int n, int t, int kk) {
    long hoff = ((long)b*NN + n)*64;
    if (CIN == 2) {
        if (kk >= 132) return 0.0f;
        long xoff = ((long)b*TT + t)*NN*2 + (long)n*2;
        if (kk < 2)   return xext[xoff + kk];
        if (kk < 66)  return (MODE ? g_zh0 : g_h0)[hoff + (kk - 2)];
        if (kk < 68)  return g_Gx2[xoff + (kk - 66)];
        return (MODE ? g_Gzh0 : g_Gh0)[hoff + (kk - 68)];
    } else {
        long xoff = ((long)b*TT + t)*NN*64 + (long)n*64;
        if (kk < 64)  return g_seq0[xoff + kk];
        if (kk < 128) return (MODE ? g_zh1 : g_h1)[hoff + (kk - 64)];
        if (kk < 192) return g_Gxall[xoff + (kk - 128)];
        return (MODE ? g_Gzh1 : g_Gh1)[hoff + (kk - 192)];
    }
}

// ---------------------------------------------------------------------------
// pre1_k: h-independent GEMM partials for layer1 (k-tiles {0,1,4,5}).
// grid (NN, 2bh, 3): z=0 gate o[0:64), z=1 gate o[64:128), z=2 cand o[0:64).
// ---------------------------------------------------------------------------
__global__ void __launch_bounds__(128, 8) pre1_k(int t) {
    int z  = blockIdx.z;
    const float* W = (z < 2) ? g_Wg1 : g_Wu1;
    int CO = (z < 2) ? 128 : 64;
    int oc0 = (z == 1) ? 64 : 0;

    int n  = blockIdx.x;
    int bh = blockIdx.y;
    int tid = threadIdx.x;
    int tx = tid & 15;
    int ty = tid >> 4;

    __shared__ float As[32][68];
    __shared__ float Ws[32][68];

    unsigned long long acc2[8][2];
#pragma unroll
    for (int i = 0; i < 8; i++) { acc2[i][0] = 0ull; acc2[i][1] = 0ull; }

    const int kts[4] = {0, 1, 4, 5};
#pragma unroll
    for (int kt = 0; kt < 4; kt++) {
        int k0 = kts[kt] * 32;
#pragma unroll
        for (int j = 0; j < 16; j++) {
            int lin = tid + j*128;
            int kl = lin & 31;
            int b  = lin >> 5;
            As[kl][b] = gatherA<64,0>(nullptr, bh*64 + b, n, t, k0 + kl);
        }
#pragma unroll
        for (int j = 0; j < 4; j++) {
            int lin = tid + j*128;
            int c4  = lin & 15;
            int row = lin >> 4;
            int kk = k0 + row;
            float4 v = *(const float4*)&W[((long)n*256 + kk)*CO + oc0 + c4*4];
            *(float4*)&Ws[row][c4*4] = v;
        }
        __syncthreads();
#pragma unroll
        for (int k = 0; k < 32; k++) {
            float4 aLo = *(const float4*)&As[k][ty*8];
            float4 aHi = *(const float4*)&As[k][ty*8 + 4];
            ulonglong2 w2 = *(const ulonglong2*)&Ws[k][tx*4];
            float av[8] = {aLo.x, aLo.y, aLo.z, aLo.w,
                           aHi.x, aHi.y, aHi.z, aHi.w};
#pragma unroll
            for (int i = 0; i < 8; i++) {
                unsigned long long ad = pk2(av[i], av[i]);
                acc2[i][0] = ffma2(ad, w2.x, acc2[i][0]);
                acc2[i][1] = ffma2(ad, w2.y, acc2[i][1]);
            }
        }
        __syncthreads();
    }

#pragma unroll
    for (int i = 0; i < 8; i++) {
        int b = bh*64 + ty*8 + i;
        float v0, v1, v2, v3;
        unpk2(acc2[i][0], v0, v1);
        unpk2(acc2[i][1], v2, v3);
        long base = ((long)(b*TT + t)*NN + n);
        if (z < 2)
            *(float4*)&g_preg1[base*128 + oc0 + tx*4] = make_float4(v0, v1, v2, v3);
        else
            *(float4*)&g_preu1[base*64 + tx*4] = make_float4(v0, v1, v2, v3);
    }
}

// ---------------------------------------------------------------------------
// Gate GEMM, oh-merged: tile 64b x 128o, 256 threads, 8b x 4o per thread.
// CIN==64: only h-dependent k-tiles {2,3,6,7}; adds pre partial in epilogue.
// ---------------------------------------------------------------------------
template<int CIN>
__global__ void __launch_bounds__(256, 4) gate_k(const float* __restrict__ xext, int t) {
    constexpr int KD  = 2*CIN + 2*DOUT;
    constexpr int NKT = (CIN == 2) ? 5 : 4;
    const float* W    = (CIN == 2) ? g_Wg0 : g_Wg1;
    const float* bias = (CIN == 2) ? g_bg0 : g_bg1;
    const float* hbuf = (CIN == 2) ? g_h0  : g_h1;
    float* zhbuf      = (CIN == 2) ? g_zh0 : g_zh1;
    float* rbuf       = (CIN == 2) ? g_r0  : g_r1;

    int n  = blockIdx.x;
    int bh = blockIdx.y;
    int tid = threadIdx.x;
    int tx = tid & 31;          // o group (4 cols, 32 groups = 128 o)
    int ty = tid >> 5;          // b group (8 rows)

    __shared__ float As[32][68];    // [kk][b]
    __shared__ float Ws[32][132];   // [kk][o]

    unsigned long long acc2[8][2];
#pragma unroll
    for (int i = 0; i < 8; i++) { acc2[i][0] = 0ull; acc2[i][1] = 0ull; }

    const int kts1[4] = {2, 3, 6, 7};
    for (int kt = 0; kt < NKT; kt++) {
        int k0 = (CIN == 2) ? kt*32 : kts1[kt]*32;
#pragma unroll
        for (int j = 0; j < 8; j++) {
            int lin = tid + j*256;
            int kl = lin & 31;
            int b  = lin >> 5;
            As[kl][b] = gatherA<CIN,0>(xext, bh*64 + b, n, t, k0 + kl);
        }
#pragma unroll
        for (int j = 0; j < 4; j++) {
            int lin = tid + j*256;
            int c4  = lin & 31;
            int row = lin >> 5;
            int kk = k0 + row;
            float4 v = make_float4(0.f, 0.f, 0.f, 0.f);
            if (kk < KD)
                v = *(const float4*)&W[((long)n*KD + kk)*128 + c4*4];
            *(float4*)&Ws[row][c4*4] = v;
        }
        __syncthreads();
#pragma unroll
        for (int k = 0; k < 32; k++) {
            float4 aLo = *(const float4*)&As[k][ty*8];
            float4 aHi = *(const float4*)&As[k][ty*8 + 4];
            ulonglong2 w2 = *(const ulonglong2*)&Ws[k][tx*4];
            float av[8] = {aLo.x, aLo.y, aLo.z, aLo.w,
                           aHi.x, aHi.y, aHi.z, aHi.w};
#pragma unroll
            for (int i = 0; i < 8; i++) {
                unsigned long long ad = pk2(av[i], av[i]);
                acc2[i][0] = ffma2(ad, w2.x, acc2[i][0]);
                acc2[i][1] = ffma2(ad, w2.y, acc2[i][1]);
            }
        }
        __syncthreads();
    }

    int o0 = tx*4;
    float4 bv = *(const float4*)&bias[n*128 + o0];
    bool isZ = (o0 < 64);
    int oc = isZ ? o0 : (o0 - 64);
#pragma unroll
    for (int i = 0; i < 8; i++) {
        int b = bh*64 + ty*8 + i;
        long hb = ((long)b*NN + n)*64 + oc;
        float v0, v1, v2, v3;
        unpk2(acc2[i][0], v0, v1);
        unpk2(acc2[i][1], v2, v3);
        if (CIN == 64) {
            float4 pv = *(const float4*)
                &g_preg1[((long)(b*TT + t)*NN + n)*128 + o0];
            v0 += pv.x; v1 += pv.y; v2 += pv.z; v3 += pv.w;
        }
        v0 = sigm(v0 + bv.x); v1 = sigm(v1 + bv.y);
        v2 = sigm(v2 + bv.z); v3 = sigm(v3 + bv.w);
        if (isZ) {
            float4 hv = *(const float4*)&hbuf[hb];
            *(float4*)&zhbuf[hb] = make_float4(v0*hv.x, v1*hv.y, v2*hv.z, v3*hv.w);
        } else {
            *(float4*)&rbuf[hb] = make_float4(v0, v1, v2, v3);
        }
    }
}

// ---------------------------------------------------------------------------
// Candidate GEMM + GRU update. CIN==64: k-tiles {2,3,6,7} + pre partial.
// tile 64b x 64o, grid (NN, 2).
// ---------------------------------------------------------------------------
template<int CIN>
__global__ void __launch_bounds__(128, 8) cand_k(const float* __restrict__ xext, int t,
                                                 float* __restrict__ curOut,
                                                 float* __restrict__ lastOut) {
    constexpr int KD  = 2*CIN + 2*DOUT;
    constexpr int NKT = (CIN == 2) ? 5 : 4;
    const float* W    = (CIN == 2) ? g_Wu0 : g_Wu1;
    const float* bias = (CIN == 2) ? g_bu0 : g_bu1;
    float* hbuf       = (CIN == 2) ? g_h0  : g_h1;
    const float* rbuf = (CIN == 2) ? g_r0  : g_r1;

    int n  = blockIdx.x;
    int bh = blockIdx.y;
    int tid = threadIdx.x;
    int tx = tid & 15;
    int ty = tid >> 4;

    __shared__ float As[32][68];
    __shared__ float Ws[32][68];

    unsigned long long acc2[8][2];
#pragma unroll
    for (int i = 0; i < 8; i++) { acc2[i][0] = 0ull; acc2[i][1] = 0ull; }

    const int kts1[4] = {2, 3, 6, 7};
    for (int kt = 0; kt < NKT; kt++) {
        int k0 = (CIN == 2) ? kt*32 : kts1[kt]*32;
#pragma unroll
        for (int j = 0; j < 16; j++) {
            int lin = tid + j*128;
            int kl = lin & 31;
            int b  = lin >> 5;
            As[kl][b] = gatherA<CIN,1>(xext, bh*64 + b, n, t, k0 + kl);
        }
#pragma unroll
        for (int j = 0; j < 4; j++) {
            int lin = tid + j*128;
            int c4  = lin & 15;
            int row = lin >> 4;
            int kk = k0 + row;
            float4 v = make_float4(0.f, 0.f, 0.f, 0.f);
            if (kk < KD)
                v = *(const float4*)&W[((long)n*KD + kk)*64 + c4*4];
            *(float4*)&Ws[row][c4*4] = v;
        }
        __syncthreads();
#pragma unroll
        for (int k = 0; k < 32; k++) {
            float4 aLo = *(const float4*)&As[k][ty*8];
            float4 aHi = *(const float4*)&As[k][ty*8 + 4];
            ulonglong2 w2 = *(const ulonglong2*)&Ws[k][tx*4];
            float av[8] = {aLo.x, aLo.y, aLo.z, aLo.w,
                           aHi.x, aHi.y, aHi.z, aHi.w};
#pragma unroll
            for (int i = 0; i < 8; i++) {
                unsigned long long ad = pk2(av[i], av[i]);
                acc2[i][0] = ffma2(ad, w2.x, acc2[i][0]);
                acc2[i][1] = ffma2(ad, w2.y, acc2[i][1]);
            }
        }
        __syncthreads();
    }

    float4 bv = *(const float4*)&bias[n*64 + tx*4];
#pragma unroll
    for (int i = 0; i < 8; i++) {
        int b = bh*64 + ty*8 + i;
        long hb = ((long)b*NN + n)*64 + tx*4;
        float c0, c1, c2, c3;
        unpk2(acc2[i][0], c0, c1);
        unpk2(acc2[i][1], c2, c3);
        if (CIN == 64) {
            float4 pv = *(const float4*)
                &g_preu1[((long)(b*TT + t)*NN + n)*64 + tx*4];
            c0 += pv.x; c1 += pv.y; c2 += pv.z; c3 += pv.w;
        }
        c0 = tanhf(c0 + bv.x); c1 = tanhf(c1 + bv.y);
        c2 = tanhf(c2 + bv.z); c3 = tanhf(c3 + bv.w);
        float4 rv = *(const float4*)&rbuf[hb];
        float4 hv = *(const float4*)&hbuf[hb];
        float4 o;
        o.x = rv.x*hv.x + (1.0f - rv.x)*c0;
        o.y = rv.y*hv.y + (1.0f - rv.y)*c1;
        o.z = rv.z*hv.z + (1.0f - rv.z)*c2;
        o.w = rv.w*hv.w + (1.0f - rv.w)*c3;
        *(float4*)&hbuf[hb] = o;
        float* seq = (CIN == 2) ? g_seq0 : curOut;
        *(float4*)&seq[((long)(b*TT + t))*NN*DOUT + (long)n*DOUT + tx*4] = o;
        if (lastOut) *(float4*)&lastOut[hb] = o;
    }
}

// ---------------------------------------------------------------------------
// Host driver — graph-capturable. Streams: layer0 on sA, Gx+pre on sC,
// layer1 on sB.
// ---------------------------------------------------------------------------
extern "C" void kernel_launch(void* const* d_in, const int* in_sizes, int n_in,
                              void* d_out, int out_size) {
    const float* x    = (const float*)d_in[0];
    const float* init = (const float*)d_in[1];
    const float* E    = (const float*)d_in[2];
    const float* adj  = (const float*)d_in[3];
    const float* wg0  = (const float*)d_in[4];
    const float* bg0  = (const float*)d_in[5];
    const float* wu0  = (const float*)d_in[6];
    const float* bu0  = (const float*)d_in[7];
    const float* wg1  = (const float*)d_in[8];
    const float* bg1  = (const float*)d_in[9];
    const float* wu1  = (const float*)d_in[10];
    const float* bu1  = (const float*)d_in[11];

    float* out      = (float*)d_out;
    float* lastBase = out + (long)CURSZ;

    static cudaStream_t sA = nullptr, sB = nullptr, sC = nullptr;
    static cudaEvent_t eFork = nullptr, eA = nullptr, eB = nullptr;
    static cudaEvent_t e0[TT], eC[TT];
    if (!sA) {
        cudaStreamCreateWithFlags(&sA, cudaStreamNonBlocking);
        cudaStreamCreateWithFlags(&sB, cudaStreamNonBlocking);
        cudaStreamCreateWithFlags(&sC, cudaStreamNonBlocking);
        cudaEventCreateWithFlags(&eFork, cudaEventDisableTiming);
        cudaEventCreateWithFlags(&eA, cudaEventDisableTiming);
        cudaEventCreateWithFlags(&eB, cudaEventDisableTiming);
        for (int t = 0; t < TT; t++) {
            cudaEventCreateWithFlags(&e0[t], cudaEventDisableTiming);
            cudaEventCreateWithFlags(&eC[t], cudaEventDisableTiming);
        }
    }

    // ---- prelude on the capture (default) stream ----
    prep_all<<<(unsigned)((C7 + 255) / 256), 256>>>(E, wg0, wu0, wg1, wu1,
                                                    bg0, bu0, bg1, bu1);
    prep_adjB<<<(NNP*NNP + 255) / 256, 256>>>(adj);
    init_h<<<dim3((BND + 255) / 256, 2), 256>>>(init);
    graph_x2_all<<<dim3(5, BT/64), 256>>>(adj, x);

    cudaEventRecord(eFork, 0);
    cudaStreamWaitEvent(sA, eFork, 0);
    cudaStreamWaitEvent(sB, eFork, 0);
    cudaStreamWaitEvent(sC, eFork, 0);

    dim3 gGrid(5, BB);   // graph64_mma: 640 blocks x 256 thr

    // ---- layer 0 on sA ----
    for (int t = 0; t < TT; t++) {
        graph64_mma<<<gGrid, 256, 0, sA>>>(0, t, 0);                    // Gh0
        gate_k<2><<<dim3(NN,2), 256, 0, sA>>>(x, t);                    // z*h, r
        graph64_mma<<<gGrid, 256, 0, sA>>>(1, t, 1);                    // Gzh0
        cand_k<2><<<dim3(NN,2), 128, 0, sA>>>(x, t, nullptr,
                        (t == TT-1) ? lastBase : nullptr);              // h0', seq0[t]
        cudaEventRecord(e0[t], sA);
    }
    // ---- Gx + h-independent partials on sC ----
    for (int t = 0; t < TT; t++) {
        cudaStreamWaitEvent(sC, e0[t], 0);
        graph64_mma<<<gGrid, 256, 0, sC>>>(2, t, 2);                    // Gxall[t]
        pre1_k<<<dim3(NN, 2, 3), 128, 0, sC>>>(t);                      // preg1/preu1[t]
        cudaEventRecord(eC[t], sC);
    }
    // ---- layer 1 on sB ----
    for (int t = 0; t < TT; t++) {
        graph64_mma<<<gGrid, 256, 0, sB>>>(3, t, 3);                    // Gh1
        cudaStreamWaitEvent(sB, eC[t], 0);                              // pre[t], Gxall[t]
        gate_k<64><<<dim3(NN,2), 256, 0, sB>>>(nullptr, t);             // K=128 + pre
        graph64_mma<<<gGrid, 256, 0, sB>>>(4, t, 4);                    // Gzh1
        cand_k<64><<<dim3(NN,2), 128, 0, sB>>>(nullptr, t, out,
                        (t == TT-1) ? lastBase + BND : nullptr);        // K=128 + pre
    }

    cudaEventRecord(eA, sA);
    cudaEventRecord(eB, sB);
    cudaStreamWaitEvent(0, eA, 0);
    cudaStreamWaitEvent(0, eB, 0);
}